// round 13
// baseline (speedup 1.0000x reference)
#include <cuda_runtime.h>
#include <cuda_fp16.h>
#include <cstdint>

#define DIN       128
#define TILE_B    64
#define NTHREADS  512
#define AST       136     // half stride
#define HKST      264
#define NTILES    20
#define TEMP_INV  0.17677669529663687f
#define LN_EPS    1e-5f

// smem: sX 17408B + sY 17408B + sWp 8*2*(16*136h)=69632B + sHk 33792B + sRk 33792B
//       + sHX 2048B + sRX 2048B + sP 4096B = 180224B
#define SMEM_BYTES 180224

__device__ __half g_Wx[1280 * DIN];
__device__ __half g_Wy[1280 * DIN];

__global__ void prep_kernel(const float* __restrict__ w_h, const float* __restrict__ w_r,
                            const float* __restrict__ k_h, const float* __restrict__ k_r) {
    int row = blockIdx.x;
    const float* w; const float* kk; __half* dst;
    if (row < 1280) { w = w_h; kk = k_h; dst = g_Wx + (size_t)row * DIN; }
    else { row -= 1280; w = w_r; kk = k_r; dst = g_Wy + (size_t)row * DIN; }
    int k = threadIdx.x;
    float v;
    if (row < 1024) v = w[(size_t)row * DIN + k];
    else {
        int h = (row - 1024) >> 5, i = (row - 1024) & 31;
        const float* wr = w + (size_t)h * DIN * DIN;
        const float* kr = kk + (size_t)i * DIN;
        float acc = 0.f;
#pragma unroll 8
        for (int j = 0; j < DIN; j++) acc = fmaf(kr[j], wr[(size_t)j * DIN + k], acc);
        v = acc;
    }
    dst[k] = __float2half_rn(v);
}

// ---------------- helpers ----------------
__device__ __forceinline__ uint32_t smem_u32(const void* p) {
    return (uint32_t)__cvta_generic_to_shared(p);
}
__device__ __forceinline__ void ldsm4(uint32_t r[4], uint32_t addr) {
    asm volatile("ldmatrix.sync.aligned.m8n8.x4.shared.b16 {%0,%1,%2,%3}, [%4];"
                 : "=r"(r[0]), "=r"(r[1]), "=r"(r[2]), "=r"(r[3]) : "r"(addr));
}
__device__ __forceinline__ void mma16816(float c[4], const uint32_t a[4], uint32_t b0, uint32_t b1) {
    asm volatile(
        "mma.sync.aligned.m16n8k16.row.col.f32.f16.f16.f32 "
        "{%0,%1,%2,%3}, {%4,%5,%6,%7}, {%8,%9}, {%0,%1,%2,%3};"
        : "+f"(c[0]), "+f"(c[1]), "+f"(c[2]), "+f"(c[3])
        : "r"(a[0]), "r"(a[1]), "r"(a[2]), "r"(a[3]), "r"(b0), "r"(b1));
}
__device__ __forceinline__ void bar_pair(int id) {
    asm volatile("bar.sync %0, 64;" :: "r"(id) : "memory");
}
#define CP_COMMIT() asm volatile("cp.async.commit_group;" ::: "memory")

__device__ __forceinline__ const __half* tile_src(int it) {
    if (it < 4) return ((it >> 1) ? g_Wy : g_Wx) + (size_t)(1024 + (it & 1) * DIN) * DIN;
    int h = it - 4;
    return (h < 8) ? g_Wx + (size_t)h * DIN * DIN : g_Wy + (size_t)(h - 8) * DIN * DIN;
}
__device__ __forceinline__ int tile_side(int it) {
    return (it < 4) ? (it >> 1) : ((it - 4) >> 3);
}

// pair stages its 16 (out-col) rows x 128 K slice; 64 threads, 4 x 16B each
__device__ __forceinline__ void stage_slice(const __half* __restrict__ tile, int ni,
                                            __half* dst, int ptid) {
    const __half* src = tile + (size_t)(ni * 16) * DIN;
    uint32_t d = smem_u32(dst);
#pragma unroll
    for (int k = 0; k < 4; k++) {
        int i = ptid + k * 64;
        int n = i >> 4, c = (i & 15) * 8;
        asm volatile("cp.async.cg.shared.global [%0], [%1], 16;" ::
                     "r"(d + (uint32_t)(n * AST + c) * 2), "l"(src + n * DIN + c));
    }
}

__device__ __forceinline__ void load_afrag(const __half* sA, int mi, int lane, uint32_t af[2][8][4]) {
#pragma unroll
    for (int s = 0; s < 2; s++) {
        int row = mi * 32 + s * 16 + (lane & 7) + ((lane >> 3) & 1) * 8;
        int coff = ((lane >> 4) & 1) * 8;
        uint32_t base = smem_u32(sA + row * AST + coff);
#pragma unroll
        for (int ks = 0; ks < 8; ks++) ldsm4(af[s][ks], base + ks * 32);
    }
}

// 32m x 16n x 128k warp gemm on pair-private 16-row B buffer
__device__ __forceinline__ void gemm_w(const uint32_t af[2][8][4], const __half* sW,
                                       int lane, float acc[2][2][4]) {
    int brow = (lane & 7) + ((lane >> 4) & 1) * 8;
    int bcoff = ((lane >> 3) & 1) * 8;
    uint32_t b = smem_u32(sW + brow * AST + bcoff);
    uint32_t bb[2][4];
    ldsm4(bb[0], b);
#pragma unroll
    for (int ks = 0; ks < 8; ks++) {
        int cur = ks & 1;
        if (ks < 7) ldsm4(bb[cur ^ 1], b + (ks + 1) * 32);
        mma16816(acc[0][0], af[0][ks], bb[cur][0], bb[cur][1]);
        mma16816(acc[0][1], af[0][ks], bb[cur][2], bb[cur][3]);
        mma16816(acc[1][0], af[1][ks], bb[cur][0], bb[cur][1]);
        mma16816(acc[1][1], af[1][ks], bb[cur][2], bb[cur][3]);
    }
}

__global__ __launch_bounds__(NTHREADS, 1)
void xattn_main(const float* __restrict__ h_emb, const float* __restrict__ r_emb,
                const float* __restrict__ gamma, const float* __restrict__ beta,
                float* __restrict__ out) {
    extern __shared__ char smem_raw[];
    __half* sX = (__half*)smem_raw;                 // 64*136
    __half* sY = sX + TILE_B * AST;                 // 64*136
    __half* sWp = sY + TILE_B * AST;                // 8 pairs x 2 bufs x 16*136
    __half* sHk = sWp + 16 * 16 * AST;              // 64*264
    __half* sRk = sHk + TILE_B * HKST;              // 64*264
    float* sHX = (float*)(sRk + TILE_B * HKST);     // 64*8
    float* sRX = sHX + TILE_B * 8;                  // 64*8
    float* sP = sRX + TILE_B * 8;                   // 16*64
    float* sT = (float*)sHk;                        // f32 alias, stride 132

    int tid = threadIdx.x;
    int warp = tid >> 5, lane = tid & 31;
    // SMSP-aware mapping: pair ni = warps {2ni, 2ni+1}; each SMSP hosts 4 distinct pairs
    int mi = warp & 1, ni = warp >> 1;
    int g = lane >> 2, t = lane & 3;
    int ptid = mi * 32 + lane;                      // 0..63 within pair
    int barid = 1 + ni;
    int row0 = blockIdx.x * TILE_B;
    __half* myW = sWp + ni * 2 * 16 * AST;          // my pair's two buffers

    // prologue: pair stages its slices of tiles 0 and 1
    stage_slice(tile_src(0), ni, myW, ptid); CP_COMMIT();
    stage_slice(tile_src(1), ni, myW + 16 * AST, ptid); CP_COMMIT();

    // load X,Y -> fp16 smem
#pragma unroll
    for (int k = 0; k < 4; k++) {
        int i = tid + k * NTHREADS;
        int r = i >> 5, c4 = i & 31;
        float4 vx = ((const float4*)(h_emb + (size_t)(row0 + r) * DIN))[c4];
        float4 vy = ((const float4*)(r_emb + (size_t)(row0 + r) * DIN))[c4];
        __half2* px = (__half2*)(sX + r * AST + c4 * 4);
        __half2* py = (__half2*)(sY + r * AST + c4 * 4);
        px[0] = __floats2half2_rn(vx.x, vx.y);
        px[1] = __floats2half2_rn(vx.z, vx.w);
        py[0] = __floats2half2_rn(vy.x, vy.y);
        py[1] = __floats2half2_rn(vy.z, vy.w);
    }
    __syncthreads();

    uint32_t af[2][8][4];
    load_afrag(sX, mi, lane, af);
    int cur_side = 0;

    float outacc[2][2][4];
#pragma unroll
    for (int s = 0; s < 2; s++)
#pragma unroll
        for (int n8 = 0; n8 < 2; n8++)
#pragma unroll
            for (int q = 0; q < 4; q++) outacc[s][n8][q] = 0.f;

#pragma unroll 1
    for (int it = 0; it < NTILES; it++) {
        // -------- attention: full-block convergence once --------
        if (it == 4) {
            __syncthreads();
            int h0 = lane >> 3, j0 = lane & 7;
#pragma unroll 1
            for (int rr = 0; rr < 4; rr++) {
                int r = warp * 4 + rr;
                const __half2* hp0 = (const __half2*)(sHk + r * HKST + h0 * 32);
                const __half2* hp1 = (const __half2*)(sHk + r * HKST + (h0 + 4) * 32);
                const __half2* rp = (const __half2*)(sRk + r * HKST + j0 * 32);
                float l0 = 0.f, l1 = 0.f;
#pragma unroll
                for (int k2 = 0; k2 < 16; k2++) {
                    float2 bb = __half22float2(rp[k2]);
                    float2 aa = __half22float2(hp0[k2]);
                    float2 cc = __half22float2(hp1[k2]);
                    l0 = fmaf(aa.x, bb.x, fmaf(aa.y, bb.y, l0));
                    l1 = fmaf(cc.x, bb.x, fmaf(cc.y, bb.y, l1));
                }
                float m = fmaxf(l0, l1);
#pragma unroll
                for (int o = 16; o; o >>= 1) m = fmaxf(m, __shfl_xor_sync(0xffffffffu, m, o));
                float e0 = __expf(l0 - m), e1 = __expf(l1 - m);
                float s = e0 + e1;
#pragma unroll
                for (int o = 16; o; o >>= 1) s += __shfl_xor_sync(0xffffffffu, s, o);
                float inv = 1.0f / s;
                e0 *= inv; e1 *= inv;
                sP[warp * 64 + lane] = e0;
                sP[warp * 64 + 32 + lane] = e1;
                __syncwarp();
                if (lane < 8) {
                    float hx = 0.f;
#pragma unroll
                    for (int j = 0; j < 8; j++) hx += sP[warp * 64 + lane * 8 + j];
                    sHX[r * 8 + lane] = hx;
                } else if (lane < 16) {
                    int j = lane - 8;
                    float rx = 0.f;
#pragma unroll
                    for (int h = 0; h < 8; h++) rx += sP[warp * 64 + h * 8 + j];
                    sRX[r * 8 + j] = rx;
                }
                __syncwarp();
            }
            __syncthreads();
        }

        // tile it ready: own cp.asyncs done, then pair-converge
        if (it < NTILES - 2) asm volatile("cp.async.wait_group 1;" ::: "memory");
        else                 asm volatile("cp.async.wait_group 0;" ::: "memory");
        bar_pair(barid);

        int side = tile_side(it);
        if (side != cur_side) {
            load_afrag(side ? sY : sX, mi, lane, af);
            cur_side = side;
        }
        const __half* sWc = myW + (it & 1) * 16 * AST;

        float acc[2][2][4];
#pragma unroll
        for (int s = 0; s < 2; s++)
#pragma unroll
            for (int n8 = 0; n8 < 2; n8++)
#pragma unroll
                for (int q = 0; q < 4; q++) acc[s][n8][q] = 0.f;
        gemm_w(af, sWc, lane, acc);

        if (it < 4) {
            __half* dst = side ? sRk : sHk;
            float sc = side ? 1.0f : TEMP_INV;
            int cbase = (it & 1) * 128 + ni * 16;
#pragma unroll
            for (int s = 0; s < 2; s++) {
                int r = mi * 32 + s * 16 + g;
#pragma unroll
                for (int n8 = 0; n8 < 2; n8++) {
                    int col = cbase + n8 * 8 + 2 * t;
                    *(__half2*)(dst + r * HKST + col) =
                        __floats2half2_rn(acc[s][n8][0] * sc, acc[s][n8][1] * sc);
                    *(__half2*)(dst + (r + 8) * HKST + col) =
                        __floats2half2_rn(acc[s][n8][2] * sc, acc[s][n8][3] * sc);
                }
            }
        } else {
            int h = (it - 4) & 7;
            const float* sS = side ? sRX : sHX;
#pragma unroll
            for (int s = 0; s < 2; s++) {
                int r = mi * 32 + s * 16 + g;
                float w0 = sS[r * 8 + h];
                float w1 = sS[(r + 8) * 8 + h];
#pragma unroll
                for (int n8 = 0; n8 < 2; n8++) {
                    outacc[s][n8][0] = fmaf(w0, acc[s][n8][0], outacc[s][n8][0]);
                    outacc[s][n8][1] = fmaf(w0, acc[s][n8][1], outacc[s][n8][1]);
                    outacc[s][n8][2] = fmaf(w1, acc[s][n8][2], outacc[s][n8][2]);
                    outacc[s][n8][3] = fmaf(w1, acc[s][n8][3], outacc[s][n8][3]);
                }
            }
        }

        // partner done reading buffer (it&1) -> safe to restage for tile it+2
        bar_pair(barid);
        if (it + 2 < NTILES) {
            stage_slice(tile_src(it + 2), ni, myW + (it & 1) * 16 * AST, ptid);
            CP_COMMIT();
        }
    }
    __syncthreads();

    // -------- residual add into f32 scratch --------
#pragma unroll
    for (int s = 0; s < 2; s++) {
        int r = mi * 32 + s * 16 + g;
#pragma unroll
        for (int n8 = 0; n8 < 2; n8++) {
            int c = ni * 16 + n8 * 8 + 2 * t;
            sT[r * 132 + c]     = outacc[s][n8][0] + h_emb[(size_t)(row0 + r) * DIN + c];
            sT[r * 132 + c + 1] = outacc[s][n8][1] + h_emb[(size_t)(row0 + r) * DIN + c + 1];
            sT[(r + 8) * 132 + c]     = outacc[s][n8][2] + h_emb[(size_t)(row0 + r + 8) * DIN + c];
            sT[(r + 8) * 132 + c + 1] = outacc[s][n8][3] + h_emb[(size_t)(row0 + r + 8) * DIN + c + 1];
        }
    }
    __syncthreads();

    // -------- LayerNorm: each warp 4 rows --------
#pragma unroll 1
    for (int rr = 0; rr < 4; rr++) {
        int r = warp * 4 + rr;
        float v[4];
#pragma unroll
        for (int q = 0; q < 4; q++) v[q] = sT[r * 132 + lane + q * 32];
        float sum = v[0] + v[1] + v[2] + v[3];
#pragma unroll
        for (int o = 16; o; o >>= 1) sum += __shfl_xor_sync(0xffffffffu, sum, o);
        float mean = sum * (1.0f / 128.0f);
        float sq = 0.f;
#pragma unroll
        for (int q = 0; q < 4; q++) { v[q] -= mean; sq = fmaf(v[q], v[q], sq); }
#pragma unroll
        for (int o = 16; o; o >>= 1) sq += __shfl_xor_sync(0xffffffffu, sq, o);
        float rstd = rsqrtf(sq * (1.0f / 128.0f) + LN_EPS);
#pragma unroll
        for (int q = 0; q < 4; q++) {
            int cc = lane + q * 32;
            out[(size_t)(row0 + r) * DIN + cc] = fmaf(gamma[cc], v[q] * rstd, beta[cc]);
        }
    }
}

extern "C" void kernel_launch(void* const* d_in, const int* in_sizes, int n_in,
                              void* d_out, int out_size) {
    const float* h_emb = (const float*)d_in[0];
    const float* r_emb = (const float*)d_in[1];
    const float* w_h = (const float*)d_in[2];
    const float* w_r = (const float*)d_in[3];
    const float* k_h = (const float*)d_in[4];
    const float* k_r = (const float*)d_in[5];
    const float* gamma = (const float*)d_in[6];
    const float* beta = (const float*)d_in[7];
    // d_in[8] = mode, always 0 ('normal').

    int Brows = in_sizes[0] / DIN;
    int grid = Brows / TILE_B;

    prep_kernel<<<2560, 128>>>(w_h, w_r, k_h, k_r);

    cudaFuncSetAttribute(xattn_main, cudaFuncAttributeMaxDynamicSharedMemorySize, SMEM_BYTES);
    xattn_main<<<grid, NTHREADS, SMEM_BYTES>>>(h_emb, r_emb, gamma, beta, (float*)d_out);
}

// round 14
// speedup vs baseline: 1.5257x; 1.5257x over previous
#include <cuda_runtime.h>
#include <cuda_fp16.h>
#include <cstdint>

#define DIN       128
#define TILE_B    64
#define NTHREADS  512
#define AST       136     // half stride
#define HKST      264
#define NTILES    20
#define TEMP_INV  0.17677669529663687f
#define LN_EPS    1e-5f

// smem: sX 17408B + sY 17408B + sWp 8*2*(16*136h)=69632B + sHk 33792B + sRk 33792B
//       + sHX 2048B + sRX 2048B + sP 4096B = 180224B
#define SMEM_BYTES 180224

__device__ __half g_Wx[1280 * DIN];
__device__ __half g_Wy[1280 * DIN];

__global__ void prep_kernel(const float* __restrict__ w_h, const float* __restrict__ w_r,
                            const float* __restrict__ k_h, const float* __restrict__ k_r) {
    int row = blockIdx.x;
    const float* w; const float* kk; __half* dst;
    if (row < 1280) { w = w_h; kk = k_h; dst = g_Wx + (size_t)row * DIN; }
    else { row -= 1280; w = w_r; kk = k_r; dst = g_Wy + (size_t)row * DIN; }
    int k = threadIdx.x;
    float v;
    if (row < 1024) v = w[(size_t)row * DIN + k];
    else {
        int h = (row - 1024) >> 5, i = (row - 1024) & 31;
        const float* wr = w + (size_t)h * DIN * DIN;
        const float* kr = kk + (size_t)i * DIN;
        float acc = 0.f;
#pragma unroll 8
        for (int j = 0; j < DIN; j++) acc = fmaf(kr[j], wr[(size_t)j * DIN + k], acc);
        v = acc;
    }
    dst[k] = __float2half_rn(v);
}

// ---------------- helpers ----------------
__device__ __forceinline__ uint32_t smem_u32(const void* p) {
    return (uint32_t)__cvta_generic_to_shared(p);
}
__device__ __forceinline__ void ldsm4(uint32_t r[4], uint32_t addr) {
    asm volatile("ldmatrix.sync.aligned.m8n8.x4.shared.b16 {%0,%1,%2,%3}, [%4];"
                 : "=r"(r[0]), "=r"(r[1]), "=r"(r[2]), "=r"(r[3]) : "r"(addr));
}
__device__ __forceinline__ void mma16816(float c[4], const uint32_t a[4], uint32_t b0, uint32_t b1) {
    asm volatile(
        "mma.sync.aligned.m16n8k16.row.col.f32.f16.f16.f32 "
        "{%0,%1,%2,%3}, {%4,%5,%6,%7}, {%8,%9}, {%0,%1,%2,%3};"
        : "+f"(c[0]), "+f"(c[1]), "+f"(c[2]), "+f"(c[3])
        : "r"(a[0]), "r"(a[1]), "r"(a[2]), "r"(a[3]), "r"(b0), "r"(b1));
}
__device__ __forceinline__ void bar_pair(int id) {
    asm volatile("bar.sync %0, 64;" :: "r"(id) : "memory");
}
#define CP_COMMIT() asm volatile("cp.async.commit_group;" ::: "memory")

__device__ __forceinline__ const __half* tile_src(int it) {
    if (it < 4) return ((it >> 1) ? g_Wy : g_Wx) + (size_t)(1024 + (it & 1) * DIN) * DIN;
    int h = it - 4;
    return (h < 8) ? g_Wx + (size_t)h * DIN * DIN : g_Wy + (size_t)(h - 8) * DIN * DIN;
}
__device__ __forceinline__ int tile_side(int it) {
    return (it < 4) ? (it >> 1) : ((it - 4) >> 3);
}

// pair stages its 16 (out-col) rows x 128 K slice; 64 threads, 4 x 16B each
__device__ __forceinline__ void stage_slice(const __half* __restrict__ tile, int ni,
                                            __half* dst, int ptid) {
    const __half* src = tile + (size_t)(ni * 16) * DIN;
    uint32_t d = smem_u32(dst);
#pragma unroll
    for (int k = 0; k < 4; k++) {
        int i = ptid + k * 64;
        int n = i >> 4, c = (i & 15) * 8;
        asm volatile("cp.async.cg.shared.global [%0], [%1], 16;" ::
                     "r"(d + (uint32_t)(n * AST + c) * 2), "l"(src + n * DIN + c));
    }
}

__device__ __forceinline__ void load_afrag(const __half* sA, int mi, int lane, uint32_t af[2][8][4]) {
#pragma unroll
    for (int s = 0; s < 2; s++) {
        int row = mi * 32 + s * 16 + (lane & 7) + ((lane >> 3) & 1) * 8;
        int coff = ((lane >> 4) & 1) * 8;
        uint32_t base = smem_u32(sA + row * AST + coff);
#pragma unroll
        for (int ks = 0; ks < 8; ks++) ldsm4(af[s][ks], base + ks * 32);
    }
}

// 32m x 16n x 128k warp gemm on pair-private 16-row B buffer
__device__ __forceinline__ void gemm_w(const uint32_t af[2][8][4], const __half* sW,
                                       int lane, float acc[2][2][4]) {
    int brow = (lane & 7) + ((lane >> 4) & 1) * 8;
    int bcoff = ((lane >> 3) & 1) * 8;
    uint32_t b = smem_u32(sW + brow * AST + bcoff);
    uint32_t bb[2][4];
    ldsm4(bb[0], b);
#pragma unroll
    for (int ks = 0; ks < 8; ks++) {
        int cur = ks & 1;
        if (ks < 7) ldsm4(bb[cur ^ 1], b + (ks + 1) * 32);
        mma16816(acc[0][0], af[0][ks], bb[cur][0], bb[cur][1]);
        mma16816(acc[0][1], af[0][ks], bb[cur][2], bb[cur][3]);
        mma16816(acc[1][0], af[1][ks], bb[cur][0], bb[cur][1]);
        mma16816(acc[1][1], af[1][ks], bb[cur][2], bb[cur][3]);
    }
}

__global__ __launch_bounds__(NTHREADS, 1)
void xattn_main(const float* __restrict__ h_emb, const float* __restrict__ r_emb,
                const float* __restrict__ gamma, const float* __restrict__ beta,
                float* __restrict__ out) {
    extern __shared__ char smem_raw[];
    __half* sX = (__half*)smem_raw;                 // 64*136
    __half* sY = sX + TILE_B * AST;                 // 64*136
    __half* sWp = sY + TILE_B * AST;                // 8 pairs x 2 bufs x 16*136
    __half* sHk = sWp + 16 * 16 * AST;              // 64*264
    __half* sRk = sHk + TILE_B * HKST;              // 64*264
    float* sHX = (float*)(sRk + TILE_B * HKST);     // 64*8
    float* sRX = sHX + TILE_B * 8;                  // 64*8
    float* sP = sRX + TILE_B * 8;                   // 16*64
    float* sT = (float*)sHk;                        // f32 alias, stride 132

    int tid = threadIdx.x;
    int warp = tid >> 5, lane = tid & 31;
    int mi = warp >> 3, ni = warp & 7;              // 2 x 8 warp grid (R10 mapping)
    int g = lane >> 2, t = lane & 3;
    int ptid = mi * 32 + lane;                      // 0..63 within pair
    int barid = 1 + ni;
    int row0 = blockIdx.x * TILE_B;
    __half* myW = sWp + ni * 2 * 16 * AST;          // my pair's two buffers

    // prologue: pair stages its slices of tiles 0 and 1
    stage_slice(tile_src(0), ni, myW, ptid); CP_COMMIT();
    stage_slice(tile_src(1), ni, myW + 16 * AST, ptid); CP_COMMIT();

    // load X,Y -> fp16 smem
#pragma unroll
    for (int k = 0; k < 4; k++) {
        int i = tid + k * NTHREADS;
        int r = i >> 5, c4 = i & 31;
        float4 vx = ((const float4*)(h_emb + (size_t)(row0 + r) * DIN))[c4];
        float4 vy = ((const float4*)(r_emb + (size_t)(row0 + r) * DIN))[c4];
        __half2* px = (__half2*)(sX + r * AST + c4 * 4);
        __half2* py = (__half2*)(sY + r * AST + c4 * 4);
        px[0] = __floats2half2_rn(vx.x, vx.y);
        px[1] = __floats2half2_rn(vx.z, vx.w);
        py[0] = __floats2half2_rn(vy.x, vy.y);
        py[1] = __floats2half2_rn(vy.z, vy.w);
    }
    __syncthreads();

    uint32_t af[2][8][4];
    load_afrag(sX, mi, lane, af);
    int cur_side = 0;

    float outacc[2][2][4];
#pragma unroll
    for (int s = 0; s < 2; s++)
#pragma unroll
        for (int n8 = 0; n8 < 2; n8++)
#pragma unroll
            for (int q = 0; q < 4; q++) outacc[s][n8][q] = 0.f;

#pragma unroll 2
    for (int it = 0; it < NTILES; it++) {
        // -------- attention: full-block convergence once --------
        if (it == 4) {
            __syncthreads();
            int h0 = lane >> 3, j0 = lane & 7;
#pragma unroll 1
            for (int rr = 0; rr < 4; rr++) {
                int r = warp * 4 + rr;
                const __half2* hp0 = (const __half2*)(sHk + r * HKST + h0 * 32);
                const __half2* hp1 = (const __half2*)(sHk + r * HKST + (h0 + 4) * 32);
                const __half2* rp = (const __half2*)(sRk + r * HKST + j0 * 32);
                float l0 = 0.f, l1 = 0.f;
#pragma unroll
                for (int k2 = 0; k2 < 16; k2++) {
                    float2 bb = __half22float2(rp[k2]);
                    float2 aa = __half22float2(hp0[k2]);
                    float2 cc = __half22float2(hp1[k2]);
                    l0 = fmaf(aa.x, bb.x, fmaf(aa.y, bb.y, l0));
                    l1 = fmaf(cc.x, bb.x, fmaf(cc.y, bb.y, l1));
                }
                float m = fmaxf(l0, l1);
#pragma unroll
                for (int o = 16; o; o >>= 1) m = fmaxf(m, __shfl_xor_sync(0xffffffffu, m, o));
                float e0 = __expf(l0 - m), e1 = __expf(l1 - m);
                float s = e0 + e1;
#pragma unroll
                for (int o = 16; o; o >>= 1) s += __shfl_xor_sync(0xffffffffu, s, o);
                float inv = 1.0f / s;
                e0 *= inv; e1 *= inv;
                sP[warp * 64 + lane] = e0;
                sP[warp * 64 + 32 + lane] = e1;
                __syncwarp();
                if (lane < 8) {
                    float hx = 0.f;
#pragma unroll
                    for (int j = 0; j < 8; j++) hx += sP[warp * 64 + lane * 8 + j];
                    sHX[r * 8 + lane] = hx;
                } else if (lane < 16) {
                    int j = lane - 8;
                    float rx = 0.f;
#pragma unroll
                    for (int h = 0; h < 8; h++) rx += sP[warp * 64 + h * 8 + j];
                    sRX[r * 8 + j] = rx;
                }
                __syncwarp();
            }
            __syncthreads();
        }

        // tile it ready: own cp.asyncs done, then pair-converge
        if (it < NTILES - 2) asm volatile("cp.async.wait_group 1;" ::: "memory");
        else                 asm volatile("cp.async.wait_group 0;" ::: "memory");
        bar_pair(barid);

        int side = tile_side(it);
        if (side != cur_side) {
            load_afrag(side ? sY : sX, mi, lane, af);
            cur_side = side;
        }
        const __half* sWc = myW + (it & 1) * 16 * AST;

        // prefetch phase-2 scale factors before the MMAs (hide LDS latency)
        float w0s[2], w1s[2];
        if (it >= 4) {
            int h = (it - 4) & 7;
            const float* sS = side ? sRX : sHX;
#pragma unroll
            for (int s = 0; s < 2; s++) {
                int r = mi * 32 + s * 16 + g;
                w0s[s] = sS[r * 8 + h];
                w1s[s] = sS[(r + 8) * 8 + h];
            }
        }

        float acc[2][2][4];
#pragma unroll
        for (int s = 0; s < 2; s++)
#pragma unroll
            for (int n8 = 0; n8 < 2; n8++)
#pragma unroll
                for (int q = 0; q < 4; q++) acc[s][n8][q] = 0.f;
        gemm_w(af, sWc, lane, acc);

        if (it < 4) {
            __half* dst = side ? sRk : sHk;
            float sc = side ? 1.0f : TEMP_INV;
            int cbase = (it & 1) * 128 + ni * 16;
#pragma unroll
            for (int s = 0; s < 2; s++) {
                int r = mi * 32 + s * 16 + g;
#pragma unroll
                for (int n8 = 0; n8 < 2; n8++) {
                    int col = cbase + n8 * 8 + 2 * t;
                    *(__half2*)(dst + r * HKST + col) =
                        __floats2half2_rn(acc[s][n8][0] * sc, acc[s][n8][1] * sc);
                    *(__half2*)(dst + (r + 8) * HKST + col) =
                        __floats2half2_rn(acc[s][n8][2] * sc, acc[s][n8][3] * sc);
                }
            }
        } else {
#pragma unroll
            for (int s = 0; s < 2; s++) {
#pragma unroll
                for (int n8 = 0; n8 < 2; n8++) {
                    outacc[s][n8][0] = fmaf(w0s[s], acc[s][n8][0], outacc[s][n8][0]);
                    outacc[s][n8][1] = fmaf(w0s[s], acc[s][n8][1], outacc[s][n8][1]);
                    outacc[s][n8][2] = fmaf(w1s[s], acc[s][n8][2], outacc[s][n8][2]);
                    outacc[s][n8][3] = fmaf(w1s[s], acc[s][n8][3], outacc[s][n8][3]);
                }
            }
        }

        // partner done reading buffer (it&1) -> safe to restage for tile it+2
        bar_pair(barid);
        if (it + 2 < NTILES) {
            stage_slice(tile_src(it + 2), ni, myW + (it & 1) * 16 * AST, ptid);
            CP_COMMIT();
        }
    }
    __syncthreads();

    // -------- residual add into f32 scratch --------
#pragma unroll
    for (int s = 0; s < 2; s++) {
        int r = mi * 32 + s * 16 + g;
#pragma unroll
        for (int n8 = 0; n8 < 2; n8++) {
            int c = ni * 16 + n8 * 8 + 2 * t;
            sT[r * 132 + c]     = outacc[s][n8][0] + h_emb[(size_t)(row0 + r) * DIN + c];
            sT[r * 132 + c + 1] = outacc[s][n8][1] + h_emb[(size_t)(row0 + r) * DIN + c + 1];
            sT[(r + 8) * 132 + c]     = outacc[s][n8][2] + h_emb[(size_t)(row0 + r + 8) * DIN + c];
            sT[(r + 8) * 132 + c + 1] = outacc[s][n8][3] + h_emb[(size_t)(row0 + r + 8) * DIN + c + 1];
        }
    }
    __syncthreads();

    // -------- LayerNorm: each warp 4 rows --------
#pragma unroll 1
    for (int rr = 0; rr < 4; rr++) {
        int r = warp * 4 + rr;
        float v[4];
#pragma unroll
        for (int q = 0; q < 4; q++) v[q] = sT[r * 132 + lane + q * 32];
        float sum = v[0] + v[1] + v[2] + v[3];
#pragma unroll
        for (int o = 16; o; o >>= 1) sum += __shfl_xor_sync(0xffffffffu, sum, o);
        float mean = sum * (1.0f / 128.0f);
        float sq = 0.f;
#pragma unroll
        for (int q = 0; q < 4; q++) { v[q] -= mean; sq = fmaf(v[q], v[q], sq); }
#pragma unroll
        for (int o = 16; o; o >>= 1) sq += __shfl_xor_sync(0xffffffffu, sq, o);
        float rstd = rsqrtf(sq * (1.0f / 128.0f) + LN_EPS);
#pragma unroll
        for (int q = 0; q < 4; q++) {
            int cc = lane + q * 32;
            out[(size_t)(row0 + r) * DIN + cc] = fmaf(gamma[cc], v[q] * rstd, beta[cc]);
        }
    }
}

extern "C" void kernel_launch(void* const* d_in, const int* in_sizes, int n_in,
                              void* d_out, int out_size) {
    const float* h_emb = (const float*)d_in[0];
    const float* r_emb = (const float*)d_in[1];
    const float* w_h = (const float*)d_in[2];
    const float* w_r = (const float*)d_in[3];
    const float* k_h = (const float*)d_in[4];
    const float* k_r = (const float*)d_in[5];
    const float* gamma = (const float*)d_in[6];
    const float* beta = (const float*)d_in[7];
    // d_in[8] = mode, always 0 ('normal').

    int Brows = in_sizes[0] / DIN;
    int grid = Brows / TILE_B;

    prep_kernel<<<2560, 128>>>(w_h, w_r, k_h, k_r);

    cudaFuncSetAttribute(xattn_main, cudaFuncAttributeMaxDynamicSharedMemorySize, SMEM_BYTES);
    xattn_main<<<grid, NTHREADS, SMEM_BYTES>>>(h_emb, r_emb, gamma, beta, (float*)d_out);
}

// round 15
// speedup vs baseline: 1.5396x; 1.0091x over previous
#include <cuda_runtime.h>
#include <cuda_fp16.h>
#include <cstdint>

#define DIN       128
#define TILE_B    64
#define NTHREADS  512
#define AST       136     // half stride
#define HKST      264
#define NTILES    20
#define TEMP_INV  0.17677669529663687f
#define LN_EPS    1e-5f

// smem: sX 17408B + sY 17408B + sWp 8*2*(16*136h)=69632B + sHk 33792B + sRk 33792B
//       + sHX 2048B + sRX 2048B + sP 4096B = 180224B
#define SMEM_BYTES 180224

__device__ __half g_Wx[1280 * DIN];
__device__ __half g_Wy[1280 * DIN];

__global__ void prep_kernel(const float* __restrict__ w_h, const float* __restrict__ w_r,
                            const float* __restrict__ k_h, const float* __restrict__ k_r) {
    int row = blockIdx.x;
    const float* w; const float* kk; __half* dst;
    if (row < 1280) { w = w_h; kk = k_h; dst = g_Wx + (size_t)row * DIN; }
    else { row -= 1280; w = w_r; kk = k_r; dst = g_Wy + (size_t)row * DIN; }
    int k = threadIdx.x;
    float v;
    if (row < 1024) v = w[(size_t)row * DIN + k];
    else {
        int h = (row - 1024) >> 5, i = (row - 1024) & 31;
        const float* wr = w + (size_t)h * DIN * DIN;
        const float* kr = kk + (size_t)i * DIN;
        float acc = 0.f;
#pragma unroll 8
        for (int j = 0; j < DIN; j++) acc = fmaf(kr[j], wr[(size_t)j * DIN + k], acc);
        v = acc;
    }
    dst[k] = __float2half_rn(v);
}

// ---------------- helpers ----------------
__device__ __forceinline__ uint32_t smem_u32(const void* p) {
    return (uint32_t)__cvta_generic_to_shared(p);
}
__device__ __forceinline__ void ldsm4(uint32_t r[4], uint32_t addr) {
    asm volatile("ldmatrix.sync.aligned.m8n8.x4.shared.b16 {%0,%1,%2,%3}, [%4];"
                 : "=r"(r[0]), "=r"(r[1]), "=r"(r[2]), "=r"(r[3]) : "r"(addr));
}
__device__ __forceinline__ void mma16816(float c[4], const uint32_t a[4], uint32_t b0, uint32_t b1) {
    asm volatile(
        "mma.sync.aligned.m16n8k16.row.col.f32.f16.f16.f32 "
        "{%0,%1,%2,%3}, {%4,%5,%6,%7}, {%8,%9}, {%0,%1,%2,%3};"
        : "+f"(c[0]), "+f"(c[1]), "+f"(c[2]), "+f"(c[3])
        : "r"(a[0]), "r"(a[1]), "r"(a[2]), "r"(a[3]), "r"(b0), "r"(b1));
}
__device__ __forceinline__ void bar_pair(int id) {
    asm volatile("bar.sync %0, 64;" :: "r"(id) : "memory");
}
#define CP_COMMIT() asm volatile("cp.async.commit_group;" ::: "memory")

__device__ __forceinline__ const __half* tile_src(int it) {
    if (it < 4) return ((it >> 1) ? g_Wy : g_Wx) + (size_t)(1024 + (it & 1) * DIN) * DIN;
    int h = it - 4;
    return (h < 8) ? g_Wx + (size_t)h * DIN * DIN : g_Wy + (size_t)(h - 8) * DIN * DIN;
}
__device__ __forceinline__ int tile_side(int it) {
    return (it < 4) ? (it >> 1) : ((it - 4) >> 3);
}

// pair stages its 16 (out-col) rows x 128 K slice; 64 threads, 4 x 16B each
__device__ __forceinline__ void stage_slice(const __half* __restrict__ tile, int ni,
                                            __half* dst, int ptid) {
    const __half* src = tile + (size_t)(ni * 16) * DIN;
    uint32_t d = smem_u32(dst);
#pragma unroll
    for (int k = 0; k < 4; k++) {
        int i = ptid + k * 64;
        int n = i >> 4, c = (i & 15) * 8;
        asm volatile("cp.async.cg.shared.global [%0], [%1], 16;" ::
                     "r"(d + (uint32_t)(n * AST + c) * 2), "l"(src + n * DIN + c));
    }
}

__device__ __forceinline__ void load_afrag(const __half* sA, int mi, int lane, uint32_t af[2][8][4]) {
#pragma unroll
    for (int s = 0; s < 2; s++) {
        int row = mi * 32 + s * 16 + (lane & 7) + ((lane >> 3) & 1) * 8;
        int coff = ((lane >> 4) & 1) * 8;
        uint32_t base = smem_u32(sA + row * AST + coff);
#pragma unroll
        for (int ks = 0; ks < 8; ks++) ldsm4(af[s][ks], base + ks * 32);
    }
}

// 32m x 16n x 128k warp gemm on pair-private 16-row B buffer
__device__ __forceinline__ void gemm_w(const uint32_t af[2][8][4], const __half* sW,
                                       int lane, float acc[2][2][4]) {
    int brow = (lane & 7) + ((lane >> 4) & 1) * 8;
    int bcoff = ((lane >> 3) & 1) * 8;
    uint32_t b = smem_u32(sW + brow * AST + bcoff);
    uint32_t bb[2][4];
    ldsm4(bb[0], b);
#pragma unroll
    for (int ks = 0; ks < 8; ks++) {
        int cur = ks & 1;
        if (ks < 7) ldsm4(bb[cur ^ 1], b + (ks + 1) * 32);
        mma16816(acc[0][0], af[0][ks], bb[cur][0], bb[cur][1]);
        mma16816(acc[0][1], af[0][ks], bb[cur][2], bb[cur][3]);
        mma16816(acc[1][0], af[1][ks], bb[cur][0], bb[cur][1]);
        mma16816(acc[1][1], af[1][ks], bb[cur][2], bb[cur][3]);
    }
}

__global__ __launch_bounds__(NTHREADS, 1)
void xattn_main(const float* __restrict__ h_emb, const float* __restrict__ r_emb,
                const float* __restrict__ gamma, const float* __restrict__ beta,
                float* __restrict__ out) {
    extern __shared__ char smem_raw[];
    __half* sX = (__half*)smem_raw;                 // 64*136
    __half* sY = sX + TILE_B * AST;                 // 64*136
    __half* sWp = sY + TILE_B * AST;                // 8 pairs x 2 bufs x 16*136
    __half* sHk = sWp + 16 * 16 * AST;              // 64*264
    __half* sRk = sHk + TILE_B * HKST;              // 64*264
    float* sHX = (float*)(sRk + TILE_B * HKST);     // 64*8
    float* sRX = sHX + TILE_B * 8;                  // 64*8
    float* sP = sRX + TILE_B * 8;                   // 16*64
    float* sT = (float*)sHk;                        // f32 alias, stride 132

    int tid = threadIdx.x;
    int warp = tid >> 5, lane = tid & 31;
    int mi = warp >> 3, ni = warp & 7;              // 2 x 8 warp grid (R10 mapping)
    int g = lane >> 2, t = lane & 3;
    int ptid = mi * 32 + lane;                      // 0..63 within pair
    int barid = 1 + ni;
    int row0 = blockIdx.x * TILE_B;
    __half* myW = sWp + ni * 2 * 16 * AST;          // my pair's two buffers

    // prologue: pair stages its slices of tiles 0 and 1
    stage_slice(tile_src(0), ni, myW, ptid); CP_COMMIT();
    stage_slice(tile_src(1), ni, myW + 16 * AST, ptid); CP_COMMIT();

    // load X,Y -> fp16 smem
#pragma unroll
    for (int k = 0; k < 4; k++) {
        int i = tid + k * NTHREADS;
        int r = i >> 5, c4 = i & 31;
        float4 vx = ((const float4*)(h_emb + (size_t)(row0 + r) * DIN))[c4];
        float4 vy = ((const float4*)(r_emb + (size_t)(row0 + r) * DIN))[c4];
        __half2* px = (__half2*)(sX + r * AST + c4 * 4);
        __half2* py = (__half2*)(sY + r * AST + c4 * 4);
        px[0] = __floats2half2_rn(vx.x, vx.y);
        px[1] = __floats2half2_rn(vx.z, vx.w);
        py[0] = __floats2half2_rn(vy.x, vy.y);
        py[1] = __floats2half2_rn(vy.z, vy.w);
    }
    __syncthreads();

    uint32_t af[2][8][4];
    load_afrag(sX, mi, lane, af);
    int cur_side = 0;

    float outacc[2][2][4];
#pragma unroll
    for (int s = 0; s < 2; s++)
#pragma unroll
        for (int n8 = 0; n8 < 2; n8++)
#pragma unroll
            for (int q = 0; q < 4; q++) outacc[s][n8][q] = 0.f;

#pragma unroll 4
    for (int it = 0; it < NTILES; it++) {
        // -------- attention: full-block convergence once --------
        if (it == 4) {
            __syncthreads();
            int h0 = lane >> 3, j0 = lane & 7;
#pragma unroll 1
            for (int rr = 0; rr < 4; rr++) {
                int r = warp * 4 + rr;
                const __half2* hp0 = (const __half2*)(sHk + r * HKST + h0 * 32);
                const __half2* hp1 = (const __half2*)(sHk + r * HKST + (h0 + 4) * 32);
                const __half2* rp = (const __half2*)(sRk + r * HKST + j0 * 32);
                float l0 = 0.f, l1 = 0.f;
#pragma unroll
                for (int k2 = 0; k2 < 16; k2++) {
                    float2 bb = __half22float2(rp[k2]);
                    float2 aa = __half22float2(hp0[k2]);
                    float2 cc = __half22float2(hp1[k2]);
                    l0 = fmaf(aa.x, bb.x, fmaf(aa.y, bb.y, l0));
                    l1 = fmaf(cc.x, bb.x, fmaf(cc.y, bb.y, l1));
                }
                float m = fmaxf(l0, l1);
#pragma unroll
                for (int o = 16; o; o >>= 1) m = fmaxf(m, __shfl_xor_sync(0xffffffffu, m, o));
                float e0 = __expf(l0 - m), e1 = __expf(l1 - m);
                float s = e0 + e1;
#pragma unroll
                for (int o = 16; o; o >>= 1) s += __shfl_xor_sync(0xffffffffu, s, o);
                float inv = 1.0f / s;
                e0 *= inv; e1 *= inv;
                sP[warp * 64 + lane] = e0;
                sP[warp * 64 + 32 + lane] = e1;
                __syncwarp();
                if (lane < 8) {
                    float hx = 0.f;
#pragma unroll
                    for (int j = 0; j < 8; j++) hx += sP[warp * 64 + lane * 8 + j];
                    sHX[r * 8 + lane] = hx;
                } else if (lane < 16) {
                    int j = lane - 8;
                    float rx = 0.f;
#pragma unroll
                    for (int h = 0; h < 8; h++) rx += sP[warp * 64 + h * 8 + j];
                    sRX[r * 8 + j] = rx;
                }
                __syncwarp();
            }
            __syncthreads();
        }

        // tile it ready: own cp.asyncs done, then pair-converge
        if (it < NTILES - 2) asm volatile("cp.async.wait_group 1;" ::: "memory");
        else                 asm volatile("cp.async.wait_group 0;" ::: "memory");
        bar_pair(barid);

        int side = tile_side(it);
        if (side != cur_side) {
            load_afrag(side ? sY : sX, mi, lane, af);
            cur_side = side;
        }
        const __half* sWc = myW + (it & 1) * 16 * AST;

        // prefetch phase-2 scale factors before the MMAs (hide LDS latency)
        float w0s[2], w1s[2];
        if (it >= 4) {
            int h = (it - 4) & 7;
            const float* sS = side ? sRX : sHX;
#pragma unroll
            for (int s = 0; s < 2; s++) {
                int r = mi * 32 + s * 16 + g;
                w0s[s] = sS[r * 8 + h];
                w1s[s] = sS[(r + 8) * 8 + h];
            }
        }

        float acc[2][2][4];
#pragma unroll
        for (int s = 0; s < 2; s++)
#pragma unroll
            for (int n8 = 0; n8 < 2; n8++)
#pragma unroll
                for (int q = 0; q < 4; q++) acc[s][n8][q] = 0.f;
        gemm_w(af, sWc, lane, acc);

        if (it < 4) {
            __half* dst = side ? sRk : sHk;
            float sc = side ? 1.0f : TEMP_INV;
            int cbase = (it & 1) * 128 + ni * 16;
#pragma unroll
            for (int s = 0; s < 2; s++) {
                int r = mi * 32 + s * 16 + g;
#pragma unroll
                for (int n8 = 0; n8 < 2; n8++) {
                    int col = cbase + n8 * 8 + 2 * t;
                    *(__half2*)(dst + r * HKST + col) =
                        __floats2half2_rn(acc[s][n8][0] * sc, acc[s][n8][1] * sc);
                    *(__half2*)(dst + (r + 8) * HKST + col) =
                        __floats2half2_rn(acc[s][n8][2] * sc, acc[s][n8][3] * sc);
                }
            }
        } else {
#pragma unroll
            for (int s = 0; s < 2; s++) {
#pragma unroll
                for (int n8 = 0; n8 < 2; n8++) {
                    outacc[s][n8][0] = fmaf(w0s[s], acc[s][n8][0], outacc[s][n8][0]);
                    outacc[s][n8][1] = fmaf(w0s[s], acc[s][n8][1], outacc[s][n8][1]);
                    outacc[s][n8][2] = fmaf(w1s[s], acc[s][n8][2], outacc[s][n8][2]);
                    outacc[s][n8][3] = fmaf(w1s[s], acc[s][n8][3], outacc[s][n8][3]);
                }
            }
        }

        // partner done reading buffer (it&1) -> safe to restage for tile it+2
        bar_pair(barid);
        if (it + 2 < NTILES) {
            stage_slice(tile_src(it + 2), ni, myW + (it & 1) * 16 * AST, ptid);
            CP_COMMIT();
        }
    }
    __syncthreads();

    // -------- residual add into f32 scratch --------
#pragma unroll
    for (int s = 0; s < 2; s++) {
        int r = mi * 32 + s * 16 + g;
#pragma unroll
        for (int n8 = 0; n8 < 2; n8++) {
            int c = ni * 16 + n8 * 8 + 2 * t;
            sT[r * 132 + c]     = outacc[s][n8][0] + h_emb[(size_t)(row0 + r) * DIN + c];
            sT[r * 132 + c + 1] = outacc[s][n8][1] + h_emb[(size_t)(row0 + r) * DIN + c + 1];
            sT[(r + 8) * 132 + c]     = outacc[s][n8][2] + h_emb[(size_t)(row0 + r + 8) * DIN + c];
            sT[(r + 8) * 132 + c + 1] = outacc[s][n8][3] + h_emb[(size_t)(row0 + r + 8) * DIN + c + 1];
        }
    }
    __syncthreads();

    // -------- LayerNorm: each warp 4 rows --------
#pragma unroll 1
    for (int rr = 0; rr < 4; rr++) {
        int r = warp * 4 + rr;
        float v[4];
#pragma unroll
        for (int q = 0; q < 4; q++) v[q] = sT[r * 132 + lane + q * 32];
        float sum = v[0] + v[1] + v[2] + v[3];
#pragma unroll
        for (int o = 16; o; o >>= 1) sum += __shfl_xor_sync(0xffffffffu, sum, o);
        float mean = sum * (1.0f / 128.0f);
        float sq = 0.f;
#pragma unroll
        for (int q = 0; q < 4; q++) { v[q] -= mean; sq = fmaf(v[q], v[q], sq); }
#pragma unroll
        for (int o = 16; o; o >>= 1) sq += __shfl_xor_sync(0xffffffffu, sq, o);
        float rstd = rsqrtf(sq * (1.0f / 128.0f) + LN_EPS);
#pragma unroll
        for (int q = 0; q < 4; q++) {
            int cc = lane + q * 32;
            out[(size_t)(row0 + r) * DIN + cc] = fmaf(gamma[cc], v[q] * rstd, beta[cc]);
        }
    }
}

extern "C" void kernel_launch(void* const* d_in, const int* in_sizes, int n_in,
                              void* d_out, int out_size) {
    const float* h_emb = (const float*)d_in[0];
    const float* r_emb = (const float*)d_in[1];
    const float* w_h = (const float*)d_in[2];
    const float* w_r = (const float*)d_in[3];
    const float* k_h = (const float*)d_in[4];
    const float* k_r = (const float*)d_in[5];
    const float* gamma = (const float*)d_in[6];
    const float* beta = (const float*)d_in[7];
    // d_in[8] = mode, always 0 ('normal').

    int Brows = in_sizes[0] / DIN;
    int grid = Brows / TILE_B;

    prep_kernel<<<2560, 128>>>(w_h, w_r, k_h, k_r);

    cudaFuncSetAttribute(xattn_main, cudaFuncAttributeMaxDynamicSharedMemorySize, SMEM_BYTES);
    xattn_main<<<grid, NTHREADS, SMEM_BYTES>>>(h_emb, r_emb, gamma, beta, (float*)d_out);
}